// round 15
// baseline (speedup 1.0000x reference)
#include <cuda_runtime.h>
#include <cstdint>
#include <cstddef>

// ---------------- problem constants ----------------
#define HEADS   32
#define HDIM    64
#define NSTATE  32
#define KCONV   4
#define DMODEL  2048
#define CONVDIM 2112
#define PROJW   4192
#define BATCH   4
#define LSEQ    2048
#define BL      (BATCH * LSEQ)   // 8192
#define PROJPAD 4224             // 33 * 128 (minimal pad for GEMM1 N)
#define NKT     128              // K / 16 k-tiles
#define NKT2    64               // K / 32 stage-blocks

// ---------------- scratch (device globals; no runtime alloc) ----------------
__device__ float g_proj[(size_t)BL * PROJW];       // 137 MB
__device__ float g_conv[(size_t)BL * CONVDIM];     // 69 MB
__device__ float g_dt  [(size_t)BATCH * HEADS * LSEQ];
__device__ float g_dA  [(size_t)BATCH * HEADS * LSEQ];
__device__ float g_y   [(size_t)BL * DMODEL];      // scan output (fp32 rows)
__device__ float g_xa  [(size_t)BL * DMODEL];      // packed tf32 x
__device__ float g_ya  [(size_t)BL * DMODEL];      // packed tf32 y
__device__ float g_wa  [(size_t)PROJPAD * DMODEL]; // packed tf32 W_in^T
__device__ float g_wb  [(size_t)DMODEL * DMODEL];  // packed tf32 W_out^T

// ---------------- packed fp32x2 helpers (scan) ----------------
__device__ __forceinline__ unsigned long long pack2(float lo, float hi) {
    unsigned long long r;
    asm("mov.b64 %0, {%1, %2};" : "=l"(r) : "f"(lo), "f"(hi));
    return r;
}
__device__ __forceinline__ unsigned long long mul2(unsigned long long a, unsigned long long b) {
    unsigned long long r;
    asm("mul.rn.f32x2 %0, %1, %2;" : "=l"(r) : "l"(a), "l"(b));
    return r;
}
__device__ __forceinline__ unsigned long long fma2v(unsigned long long a, unsigned long long b,
                                                    unsigned long long c) {
    unsigned long long r;
    asm("fma.rn.f32x2 %0, %1, %2, %3;" : "=l"(r) : "l"(a), "l"(b), "l"(c));
    return r;
}
__device__ __forceinline__ unsigned long long add2(unsigned long long a, unsigned long long b) {
    unsigned long long r;
    asm("add.rn.f32x2 %0, %1, %2;" : "=l"(r) : "l"(a), "l"(b));
    return r;
}
__device__ __forceinline__ float lo32(unsigned long long v) {
    return __uint_as_float((unsigned)(v & 0xffffffffull));
}
__device__ __forceinline__ float hi32(unsigned long long v) {
    return __uint_as_float((unsigned)(v >> 32));
}
__device__ __forceinline__ float tf32r(float x) {
    unsigned r;
    asm("cvt.rna.tf32.f32 %0, %1;" : "=r"(r) : "f"(x));
    return __uint_as_float(r);
}

// packed-tile float offset: r = row in 128-block, kt = k-tile, s = 16B seg, e = elem
__device__ __forceinline__ size_t pk_off(int blk, int kt, int r, int s, int e) {
    return (((size_t)blk * NKT + kt) << 11) + (size_t)r * 16 +
           (size_t)(((s + (r >> 1)) & 3) << 2) + e;
}

// ---------------- x -> packed tf32 ----------------
__global__ void round_pack_kernel(const float* __restrict__ in, float* __restrict__ out)
{
    int i = blockIdx.x * blockDim.x + threadIdx.x;
    if (i >= BL * DMODEL / 4) return;
    int m  = i >> 9;
    int sj = i & 511;
    int kt = sj >> 2, s = sj & 3;
    int mb = m >> 7,  r = m & 127;
    float4 v = ((const float4*)in)[i];
    v.x = tf32r(v.x); v.y = tf32r(v.y); v.z = tf32r(v.z); v.w = tf32r(v.w);
    size_t d = pk_off(mb, kt, r, s, 0);
    *(float4*)(out + d) = v;
}

// ---------------- W[k][n] -> packed tf32 of W^T (n-major), rows padded 0 ----------------
__global__ void transpose_pack_kernel(const float* __restrict__ in, float* __restrict__ out,
                                      int N)
{
    __shared__ float t[32][33];
    const int nb = blockIdx.x * 32;
    const int kb = blockIdx.y * 32;
    const int tx = threadIdx.x;
    const int ty = threadIdx.y;
    #pragma unroll
    for (int rr = 0; rr < 32; rr += 8) {
        int n = nb + tx;
        t[ty + rr][tx] = (n < N) ? tf32r(in[(size_t)(kb + ty + rr) * N + n]) : 0.f;
    }
    __syncthreads();
    #pragma unroll
    for (int rr = 0; rr < 32; rr += 8) {
        int n = nb + ty + rr;
        int k = kb + tx;
        float v = t[tx][ty + rr];
        out[pk_off(n >> 7, k >> 4, n & 127, (k >> 2) & 3, k & 3)] = v;
    }
}

// ================= TMA-bulk TF32 tensor-core GEMM tile (device fn) =================
#define OPER_B      16384u
#define STG_B       32768u
#define NSTG        3
#define GEMM_SMEM   (1024 + NSTG * (int)STG_B)   // 99328

__device__ __forceinline__ uint32_t smem_u32(const void* p) {
    uint32_t a;
    asm("{ .reg .u64 tmp; cvta.to.shared.u64 tmp, %1; cvt.u32.u64 %0, tmp; }"
        : "=r"(a) : "l"(p));
    return a;
}
#define LDSM4(r0, r1, r2, r3, addr) \
    asm volatile("ldmatrix.sync.aligned.m8n8.x4.shared.b16 {%0,%1,%2,%3}, [%4];\n" \
                 : "=r"(r0), "=r"(r1), "=r"(r2), "=r"(r3) : "r"(addr))
#define EXPECT_TX(bar, n) \
    asm volatile("mbarrier.arrive.expect_tx.shared.b64 _, [%0], %1;" \
                 :: "r"(bar), "r"(n) : "memory")
#define BULK16K(dst, src, bar) \
    asm volatile("cp.async.bulk.shared::cluster.global.mbarrier::complete_tx::bytes " \
                 "[%0], [%1], %2, [%3];" \
                 :: "r"(dst), "l"(src), "r"(OPER_B), "r"(bar) : "memory")
#define MBAR_WAIT(bar, par) do {                                                  \
    asm volatile("{\n\t.reg .pred P1;\n\t"                                        \
        "WL%=:\n\t"                                                               \
        "mbarrier.try_wait.parity.acquire.cta.shared::cta.b64 P1, [%0], %1, 0x989680;\n\t" \
        "@P1 bra.uni WD%=;\n\t"                                                   \
        "bra.uni WL%=;\n\t"                                                       \
        "WD%=:\n\t}"                                                              \
        :: "r"(bar), "r"(par) : "memory"); } while (0)

__device__ void gemm_tile(const float* __restrict__ Ap, const float* __restrict__ Bp,
                          const float* __restrict__ bias, float* __restrict__ C,
                          int N, int col0, int bx, int by, char* smem_raw)
{
    const uint32_t sb = smem_u32(smem_raw);
    const int tid  = threadIdx.x;
    const int warp = tid >> 5;
    const int lane = tid & 31;
    const int g    = lane >> 2;
    const int t    = lane & 3;
    const int wm   = (warp & 1) * 64;
    const int wn   = (warp >> 1) * 32;

    if (tid == 0) {
        #pragma unroll
        for (int s = 0; s < NSTG; s++) {
            asm volatile("mbarrier.init.shared.b64 [%0], %1;"
                         :: "r"(sb + s * 8), "r"(1u) : "memory");
        }
    }
    __syncthreads();

    const float* Asrc = Ap + (size_t)by * (128 * DMODEL);
    const float* Bsrc = Bp + (size_t)bx * (128 * DMODEL);

    if (tid == 0) {
        #pragma unroll
        for (int st = 0; st < NSTG - 1; st++) {
            uint32_t bar = sb + st * 8;
            uint32_t dst = sb + 1024u + (uint32_t)st * STG_B;
            EXPECT_TX(bar, 2 * OPER_B);
            BULK16K(dst,          Asrc + (size_t)st * 4096, bar);
            BULK16K(dst + OPER_B, Bsrc + (size_t)st * 4096, bar);
        }
    }

    const int aRowL = lane & 15;
    const int aSegL = lane >> 4;
    const int bRowL = (lane & 7) | ((lane & 16) >> 1);
    const int bSegL = (lane & 8) >> 3;

    float c[16][4];
    #pragma unroll
    for (int i = 0; i < 16; i++)
        #pragma unroll
        for (int j = 0; j < 4; j++) c[i][j] = 0.f;

    for (int kb = 0; kb < NKT2; kb++) {
        const int slot = kb % NSTG;
        MBAR_WAIT(sb + slot * 8, (kb / NSTG) & 1);
        __syncthreads();

        if (tid == 0 && kb + 2 < NKT2) {
            const int ns = (kb + 2) % NSTG;
            uint32_t bar = sb + ns * 8;
            uint32_t dst = sb + 1024u + (uint32_t)ns * STG_B;
            EXPECT_TX(bar, 2 * OPER_B);
            BULK16K(dst,          Asrc + (size_t)(kb + 2) * 4096, bar);
            BULK16K(dst + OPER_B, Bsrc + (size_t)(kb + 2) * 4096, bar);
        }

        const uint32_t sA = sb + 1024u + (uint32_t)slot * STG_B;
        const uint32_t sBm = sA + OPER_B;

        #pragma unroll
        for (int ks = 0; ks < 4; ks++) {
            const unsigned toff = (unsigned)(ks >> 1) * 8192u;
            unsigned a[4][4], b[4][2];
            #pragma unroll
            for (int i = 0; i < 4; i++) {
                int row = wm + i * 16 + aRowL;
                int cseg = (ks & 1) * 2 + aSegL;
                unsigned addr = sA + toff +
                    (unsigned)(row * 64 + (((cseg + ((row >> 1) & 3)) & 3) << 4));
                LDSM4(a[i][0], a[i][1], a[i][2], a[i][3], addr);
            }
            #pragma unroll
            for (int jp = 0; jp < 2; jp++) {
                int row = wn + jp * 16 + bRowL;
                int cseg = (ks & 1) * 2 + bSegL;
                unsigned addr = sBm + toff +
                    (unsigned)(row * 64 + (((cseg + ((row >> 1) & 3)) & 3) << 4));
                LDSM4(b[2*jp][0], b[2*jp][1], b[2*jp+1][0], b[2*jp+1][1], addr);
            }
            #pragma unroll
            for (int i = 0; i < 4; i++)
                #pragma unroll
                for (int j = 0; j < 4; j++) {
                    asm volatile(
                        "mma.sync.aligned.m16n8k8.row.col.f32.tf32.tf32.f32 "
                        "{%0,%1,%2,%3}, {%4,%5,%6,%7}, {%8,%9}, {%0,%1,%2,%3};\n"
                        : "+f"(c[i*4+j][0]), "+f"(c[i*4+j][1]),
                          "+f"(c[i*4+j][2]), "+f"(c[i*4+j][3])
                        : "r"(a[i][0]), "r"(a[i][1]), "r"(a[i][2]), "r"(a[i][3]),
                          "r"(b[j][0]), "r"(b[j][1]));
                }
        }
    }

    #pragma unroll
    for (int i = 0; i < 4; i++) {
        #pragma unroll
        for (int j = 0; j < 4; j++) {
            const int row = by * 128 + wm + i * 16 + g;
            const int col = col0 + bx * 128 + wn + j * 8 + 2 * t;
            if (col < N) {
                float b0 = 0.f, b1 = 0.f;
                if (bias) { b0 = __ldg(&bias[col]); b1 = __ldg(&bias[col + 1]); }
                float2 v0 = make_float2(c[i*4+j][0] + b0, c[i*4+j][1] + b1);
                float2 v1 = make_float2(c[i*4+j][2] + b0, c[i*4+j][3] + b1);
                *(float2*)&C[(size_t)row * N + col]       = v0;
                *(float2*)&C[(size_t)(row + 8) * N + col] = v1;
            }
        }
    }
}

// ---------------- selective scan block (device fn; 256-thread block, 128 active) ----------------
#define SD 8

__device__ void scan_block(const float* __restrict__ D_param, int h, int b, char* smem_raw)
{
    float* s_dt   = (float*)smem_raw;          // [LSEQ]
    float* s_dA   = s_dt + LSEQ;               // [LSEQ]
    float* s_pipe = s_dA + LSEQ;               // [SD][128]
    const int tid = threadIdx.x;

    {
        const float* dtp = g_dt + ((size_t)(b * HEADS + h)) * LSEQ;
        const float* dAp = g_dA + ((size_t)(b * HEADS + h)) * LSEQ;
        for (int i = tid; i < LSEQ; i += 256) {
            s_dt[i] = dtp[i];
            s_dA[i] = dAp[i];
        }
    }

    if (tid >= 128) {   // barrier-matching idle path
        for (int tc = 0; tc < LSEQ; tc++) __syncthreads();
        return;
    }

    const int p    = tid >> 1;
    const int half = tid & 1;
    const float Dh = D_param[h];

    unsigned long long hs[8];
    #pragma unroll
    for (int i = 0; i < 8; i++) hs[i] = 0ull;

    const bool loader = (tid < 32);
    size_t srcoff = 0; int dstoff = 0;
    if (loader) {
        if (tid < 16) { srcoff = (size_t)h * HDIM + tid * 4; dstoff = tid * 4; }
        else          { srcoff = (size_t)DMODEL + (tid - 16) * 4; dstoff = 64 + (tid - 16) * 4; }
    }
    const float* convb = g_conv + (size_t)b * LSEQ * CONVDIM;
    unsigned sbase = smem_u32(s_pipe);

    #pragma unroll
    for (int tt = 0; tt < SD - 1; tt++) {
        if (loader) {
            const float* src = convb + (size_t)tt * CONVDIM + srcoff;
            unsigned dst = sbase + (unsigned)((tt & (SD - 1)) * 128 + dstoff) * 4u;
            asm volatile("cp.async.ca.shared.global [%0], [%1], 16;\n"
                         :: "r"(dst), "l"(src));
        }
        asm volatile("cp.async.commit_group;\n" ::: "memory");
    }

    float* yout = g_y + (size_t)b * LSEQ * DMODEL + h * HDIM + p;

    for (int tc = 0; tc < LSEQ; tc++) {
        asm volatile("cp.async.wait_group 6;\n" ::: "memory");
        __syncthreads();

        const int nt = tc + SD - 1;
        if (loader && nt < LSEQ) {
            const float* src = convb + (size_t)nt * CONVDIM + srcoff;
            unsigned dst = sbase + (unsigned)((nt & (SD - 1)) * 128 + dstoff) * 4u;
            asm volatile("cp.async.ca.shared.global [%0], [%1], 16;\n"
                         :: "r"(dst), "l"(src));
        }
        asm volatile("cp.async.commit_group;\n" ::: "memory");

        const float* sl = s_pipe + (tc & (SD - 1)) * 128;
        float xv  = sl[p];
        float dtv = s_dt[tc];
        float dav = s_dA[tc];
        float coef = dtv * xv;
        unsigned long long c2 = pack2(coef, coef);
        unsigned long long d2 = pack2(dav, dav);
        const unsigned long long* B2 = (const unsigned long long*)(sl + 64) + half * 8;
        const unsigned long long* C2 = (const unsigned long long*)(sl + 96) + half * 8;

        unsigned long long acc0 = 0ull, acc1 = 0ull;
        #pragma unroll
        for (int i = 0; i < 8; i++) {
            unsigned long long u = mul2(c2, B2[i]);
            hs[i] = fma2v(d2, hs[i], u);
            if (i & 1) acc1 = fma2v(hs[i], C2[i], acc1);
            else       acc0 = fma2v(hs[i], C2[i], acc0);
        }
        unsigned long long s = add2(acc0, acc1);
        float mine = lo32(s) + hi32(s);
        float other = __shfl_xor_sync(0xffffffffu, mine, 1);
        if (half == 0) {
            yout[(size_t)tc * DMODEL] = mine + other + Dh * xv;
        }
    }
}

// ---------------- kernels ----------------
__global__ void __launch_bounds__(256, 2)
tma_gemm(const float* __restrict__ Ap, const float* __restrict__ Bp,
         const float* __restrict__ bias, float* __restrict__ C, int N, int col0)
{
    extern __shared__ __align__(16) char smem[];
    gemm_tile(Ap, Bp, bias, C, N, col0, blockIdx.x, blockIdx.y, smem);
}

// fused: bids 0..127 = scan (b,h); bids 128..1151 = gate GEMM tiles (cols 0..2048)
__global__ void __launch_bounds__(256, 2)
gate_scan(const float* __restrict__ Ap, const float* __restrict__ Bp,
          const float* __restrict__ bias, float* __restrict__ C, int N,
          const float* __restrict__ D_param)
{
    extern __shared__ __align__(16) char smem[];
    const int bid = blockIdx.x;
    if (bid < 128) {
        scan_block(D_param, bid & 31, bid >> 5, smem);
    } else {
        const int g2 = bid - 128;
        gemm_tile(Ap, Bp, bias, C, N, 0, g2 & 15, g2 >> 4, smem);
    }
}

// ---------------- causal depthwise conv1d (K=4) + SiLU ----------------
__global__ void conv_silu_kernel(const float* __restrict__ conv_w,
                                 const float* __restrict__ conv_b)
{
    int idx = blockIdx.x * blockDim.x + threadIdx.x;
    if (idx >= BL * CONVDIM) return;
    int c = idx % CONVDIM;
    int m = idx / CONVDIM;
    int l = m % LSEQ;

    float acc = conv_b[c];
    #pragma unroll
    for (int k = 0; k < KCONV; k++) {
        int lk = l - (KCONV - 1) + k;
        if (lk >= 0) {
            acc += g_proj[(size_t)(m - (KCONV - 1) + k) * PROJW + DMODEL + c]
                   * conv_w[c * KCONV + k];
        }
    }
    acc = acc / (1.f + expf(-acc));
    g_conv[(size_t)m * CONVDIM + c] = acc;
}

// ---------------- dt / dA ----------------
__global__ void dt_kernel(const float* __restrict__ A_log,
                          const float* __restrict__ dt_bias)
{
    int idx = blockIdx.x * blockDim.x + threadIdx.x;
    if (idx >= BL * HEADS) return;
    int h = idx % HEADS;
    int m = idx / HEADS;
    int b = m / LSEQ;
    int l = m % LSEQ;

    float raw = g_proj[(size_t)m * PROJW + DMODEL + CONVDIM + h] + dt_bias[h];
    float dt  = (raw > 20.f) ? raw : log1pf(expf(raw));
    float dA  = expf(dt * (-expf(A_log[h])));
    size_t o  = ((size_t)(b * HEADS + h)) * LSEQ + l;
    g_dt[o] = dt;
    g_dA[o] = dA;
}

// ---------------- gated RMSNorm -> packed tf32 y ----------------
__global__ void __launch_bounds__(256)
rmsnorm_kernel(const float* __restrict__ norm_w)
{
    const int m   = blockIdx.x;
    const int tid = threadIdx.x;
    const float* yrow = g_y    + (size_t)m * DMODEL;
    const float* grow = g_proj + (size_t)m * PROJW;

    float v[8];
    float ss = 0.f;
    #pragma unroll
    for (int k = 0; k < 8; k++) {
        int j = tid + k * 256;
        float gt  = grow[j];
        float val = yrow[j] * (gt / (1.f + expf(-gt)));
        v[k] = val;
        ss += val * val;
    }
    #pragma unroll
    for (int o = 16; o > 0; o >>= 1) ss += __shfl_xor_sync(0xffffffffu, ss, o);

    __shared__ float sred[8];
    if ((tid & 31) == 0) sred[tid >> 5] = ss;
    __syncthreads();
    float tot = sred[0] + sred[1] + sred[2] + sred[3]
              + sred[4] + sred[5] + sred[6] + sred[7];
    float scale = rsqrtf(tot * (1.f / DMODEL) + 1e-6f);

    const int mb = m >> 7, r = m & 127;
    #pragma unroll
    for (int k = 0; k < 8; k++) {
        int j = tid + k * 256;
        float val = tf32r(v[k] * scale * norm_w[j]);
        g_ya[pk_off(mb, j >> 4, r, (j >> 2) & 3, j & 3)] = val;
    }
}

// ---------------- launch ----------------
extern "C" void kernel_launch(void* const* d_in, const int* in_sizes, int n_in,
                              void* d_out, int out_size)
{
    const float* x       = (const float*)d_in[0];
    const float* W_in    = (const float*)d_in[1];
    const float* b_in    = (const float*)d_in[2];
    const float* conv_w  = (const float*)d_in[3];
    const float* conv_b  = (const float*)d_in[4];
    const float* A_log   = (const float*)d_in[5];
    const float* dt_bias = (const float*)d_in[6];
    const float* D_par   = (const float*)d_in[7];
    const float* norm_w  = (const float*)d_in[8];
    const float* W_out   = (const float*)d_in[9];
    float* out = (float*)d_out;

    float *proj, *xa, *ya, *wa, *wb;
    cudaGetSymbolAddress((void**)&proj, g_proj);
    cudaGetSymbolAddress((void**)&xa,   g_xa);
    cudaGetSymbolAddress((void**)&ya,   g_ya);
    cudaGetSymbolAddress((void**)&wa,   g_wa);
    cudaGetSymbolAddress((void**)&wb,   g_wb);

    cudaFuncSetAttribute(tma_gemm, cudaFuncAttributeMaxDynamicSharedMemorySize,
                         GEMM_SMEM);
    cudaFuncSetAttribute(gate_scan, cudaFuncAttributeMaxDynamicSharedMemorySize,
                         GEMM_SMEM);

    // 0) pack x (tf32); transpose+pack W_in, W_out
    {
        int nseg = BL * DMODEL / 4;
        round_pack_kernel<<<(nseg + 255) / 256, 256>>>(x, xa);
        dim3 blk(32, 8);
        transpose_pack_kernel<<<dim3(PROJPAD / 32, DMODEL / 32), blk>>>(W_in, wa, PROJW);
        transpose_pack_kernel<<<dim3(DMODEL / 32, DMODEL / 32), blk>>>(W_out, wb, DMODEL);
    }
    // 1) proj[:, 2048:4192] = x @ W_in[:, 2048:4192] + b_in  (17 N-tiles)
    {
        dim3 grid(17, BL / 128);
        tma_gemm<<<grid, 256, GEMM_SMEM>>>(xa, wa + (size_t)16 * 128 * DMODEL,
                                           b_in, proj, PROJW, 2048);
    }
    // 2) conv + SiLU   (needs cols 2048..4160)
    {
        int total = BL * CONVDIM;
        conv_silu_kernel<<<(total + 255) / 256, 256>>>(conv_w, conv_b);
    }
    // 3) dt / dA       (needs cols 4160..4192)
    {
        int total = BL * HEADS;
        dt_kernel<<<(total + 255) / 256, 256>>>(A_log, dt_bias);
    }
    // 4) FUSED: selective scan (bids 0..127) + gate GEMM cols 0..2048 (bids 128..1151)
    gate_scan<<<128 + 16 * (BL / 128), 256, GEMM_SMEM>>>(xa, wa, b_in, proj,
                                                         PROJW, D_par);
    // 5) gated RMSNorm (packs y as tf32)
    rmsnorm_kernel<<<BL, 256>>>(norm_w);
    // 6) out = y @ W_out
    {
        dim3 grid(DMODEL / 128, BL / 128);
        tma_gemm<<<grid, 256, GEMM_SMEM>>>(ya, wb, nullptr, out, DMODEL, 0);
    }
}

// round 16
// speedup vs baseline: 1.4533x; 1.4533x over previous
#include <cuda_runtime.h>
#include <cstdint>
#include <cstddef>

// ---------------- problem constants ----------------
#define HEADS   32
#define HDIM    64
#define NSTATE  32
#define KCONV   4
#define DMODEL  2048
#define CONVDIM 2112
#define PROJW   4192
#define BATCH   4
#define LSEQ    2048
#define BL      (BATCH * LSEQ)   // 8192
#define PROJPAD 4224             // 33 * 128
#define NKT     128
#define NKT2    64
#define NCHUNK  16
#define CLEN    128              // LSEQ / NCHUNK
#define NBH     (BATCH * HEADS)  // 128

// ---------------- scratch (device globals; no runtime alloc) ----------------
__device__ float g_proj[(size_t)BL * PROJW];
__device__ float g_conv[(size_t)BL * CONVDIM];
__device__ float g_dt  [(size_t)NBH * LSEQ];
__device__ float g_dA  [(size_t)NBH * LSEQ];
__device__ float g_y   [(size_t)BL * DMODEL];
__device__ float g_xa  [(size_t)BL * DMODEL];
__device__ float g_ya  [(size_t)BL * DMODEL];
__device__ float g_wa  [(size_t)PROJPAD * DMODEL];
__device__ float g_wb  [(size_t)DMODEL * DMODEL];
__device__ float g_hend[(size_t)NBH * NCHUNK * 2048];  // chunk-end local states
__device__ float g_hst [(size_t)NBH * NCHUNK * 2048];  // chunk-start true states
__device__ float g_aend[(size_t)NBH * NCHUNK];         // per-chunk dA product

// ---------------- packed fp32x2 helpers ----------------
__device__ __forceinline__ unsigned long long pack2(float lo, float hi) {
    unsigned long long r;
    asm("mov.b64 %0, {%1, %2};" : "=l"(r) : "f"(lo), "f"(hi));
    return r;
}
__device__ __forceinline__ unsigned long long mul2(unsigned long long a, unsigned long long b) {
    unsigned long long r;
    asm("mul.rn.f32x2 %0, %1, %2;" : "=l"(r) : "l"(a), "l"(b));
    return r;
}
__device__ __forceinline__ unsigned long long fma2v(unsigned long long a, unsigned long long b,
                                                    unsigned long long c) {
    unsigned long long r;
    asm("fma.rn.f32x2 %0, %1, %2, %3;" : "=l"(r) : "l"(a), "l"(b), "l"(c));
    return r;
}
__device__ __forceinline__ unsigned long long add2(unsigned long long a, unsigned long long b) {
    unsigned long long r;
    asm("add.rn.f32x2 %0, %1, %2;" : "=l"(r) : "l"(a), "l"(b));
    return r;
}
__device__ __forceinline__ float lo32(unsigned long long v) {
    return __uint_as_float((unsigned)(v & 0xffffffffull));
}
__device__ __forceinline__ float hi32(unsigned long long v) {
    return __uint_as_float((unsigned)(v >> 32));
}
__device__ __forceinline__ float tf32r(float x) {
    unsigned r;
    asm("cvt.rna.tf32.f32 %0, %1;" : "=r"(r) : "f"(x));
    return __uint_as_float(r);
}

// packed-tile float offset
__device__ __forceinline__ size_t pk_off(int blk, int kt, int r, int s, int e) {
    return (((size_t)blk * NKT + kt) << 11) + (size_t)r * 16 +
           (size_t)(((s + (r >> 1)) & 3) << 2) + e;
}

// ---------------- x -> packed tf32 ----------------
__global__ void round_pack_kernel(const float* __restrict__ in, float* __restrict__ out)
{
    int i = blockIdx.x * blockDim.x + threadIdx.x;
    if (i >= BL * DMODEL / 4) return;
    int m  = i >> 9;
    int sj = i & 511;
    int kt = sj >> 2, s = sj & 3;
    int mb = m >> 7,  r = m & 127;
    float4 v = ((const float4*)in)[i];
    v.x = tf32r(v.x); v.y = tf32r(v.y); v.z = tf32r(v.z); v.w = tf32r(v.w);
    *(float4*)(out + pk_off(mb, kt, r, s, 0)) = v;
}

// ---------------- W[k][n] -> packed tf32 of W^T ----------------
__global__ void transpose_pack_kernel(const float* __restrict__ in, float* __restrict__ out,
                                      int N)
{
    __shared__ float t[32][33];
    const int nb = blockIdx.x * 32;
    const int kb = blockIdx.y * 32;
    const int tx = threadIdx.x;
    const int ty = threadIdx.y;
    #pragma unroll
    for (int rr = 0; rr < 32; rr += 8) {
        int n = nb + tx;
        t[ty + rr][tx] = (n < N) ? tf32r(in[(size_t)(kb + ty + rr) * N + n]) : 0.f;
    }
    __syncthreads();
    #pragma unroll
    for (int rr = 0; rr < 32; rr += 8) {
        int n = nb + ty + rr;
        int k = kb + tx;
        out[pk_off(n >> 7, k >> 4, n & 127, (k >> 2) & 3, k & 3)] = t[tx][ty + rr];
    }
}

// ================= TMA-bulk TF32 tensor-core GEMM =================
#define OPER_B      16384u
#define STG_B       32768u
#define NSTG        3
#define GEMM_SMEM   (1024 + NSTG * (int)STG_B)

__device__ __forceinline__ uint32_t smem_u32(const void* p) {
    uint32_t a;
    asm("{ .reg .u64 tmp; cvta.to.shared.u64 tmp, %1; cvt.u32.u64 %0, tmp; }"
        : "=r"(a) : "l"(p));
    return a;
}
#define LDSM4(r0, r1, r2, r3, addr) \
    asm volatile("ldmatrix.sync.aligned.m8n8.x4.shared.b16 {%0,%1,%2,%3}, [%4];\n" \
                 : "=r"(r0), "=r"(r1), "=r"(r2), "=r"(r3) : "r"(addr))
#define EXPECT_TX(bar, n) \
    asm volatile("mbarrier.arrive.expect_tx.shared.b64 _, [%0], %1;" \
                 :: "r"(bar), "r"(n) : "memory")
#define BULK16K(dst, src, bar) \
    asm volatile("cp.async.bulk.shared::cluster.global.mbarrier::complete_tx::bytes " \
                 "[%0], [%1], %2, [%3];" \
                 :: "r"(dst), "l"(src), "r"(OPER_B), "r"(bar) : "memory")
#define MBAR_WAIT(bar, par) do {                                                  \
    asm volatile("{\n\t.reg .pred P1;\n\t"                                        \
        "WL%=:\n\t"                                                               \
        "mbarrier.try_wait.parity.acquire.cta.shared::cta.b64 P1, [%0], %1, 0x989680;\n\t" \
        "@P1 bra.uni WD%=;\n\t"                                                   \
        "bra.uni WL%=;\n\t"                                                       \
        "WD%=:\n\t}"                                                              \
        :: "r"(bar), "r"(par) : "memory"); } while (0)

__global__ void __launch_bounds__(256, 2)
tma_gemm(const float* __restrict__ Ap, const float* __restrict__ Bp,
         const float* __restrict__ bias, float* __restrict__ C, int N)
{
    extern __shared__ __align__(16) char smem[];
    const uint32_t sb = smem_u32(smem);
    const int tid  = threadIdx.x;
    const int bx   = blockIdx.x;
    const int by   = blockIdx.y;
    const int warp = tid >> 5;
    const int lane = tid & 31;
    const int g    = lane >> 2;
    const int t    = lane & 3;
    const int wm   = (warp & 1) * 64;
    const int wn   = (warp >> 1) * 32;

    if (tid == 0) {
        #pragma unroll
        for (int s = 0; s < NSTG; s++) {
            asm volatile("mbarrier.init.shared.b64 [%0], %1;"
                         :: "r"(sb + s * 8), "r"(1u) : "memory");
        }
    }
    __syncthreads();

    const float* Asrc = Ap + (size_t)by * (128 * DMODEL);
    const float* Bsrc = Bp + (size_t)bx * (128 * DMODEL);

    if (tid == 0) {
        #pragma unroll
        for (int st = 0; st < NSTG - 1; st++) {
            uint32_t bar = sb + st * 8;
            uint32_t dst = sb + 1024u + (uint32_t)st * STG_B;
            EXPECT_TX(bar, 2 * OPER_B);
            BULK16K(dst,          Asrc + (size_t)st * 4096, bar);
            BULK16K(dst + OPER_B, Bsrc + (size_t)st * 4096, bar);
        }
    }

    const int aRowL = lane & 15;
    const int aSegL = lane >> 4;
    const int bRowL = (lane & 7) | ((lane & 16) >> 1);
    const int bSegL = (lane & 8) >> 3;

    float c[16][4];
    #pragma unroll
    for (int i = 0; i < 16; i++)
        #pragma unroll
        for (int j = 0; j < 4; j++) c[i][j] = 0.f;

    for (int kb = 0; kb < NKT2; kb++) {
        const int slot = kb % NSTG;
        MBAR_WAIT(sb + slot * 8, (kb / NSTG) & 1);
        __syncthreads();

        if (tid == 0 && kb + 2 < NKT2) {
            const int ns = (kb + 2) % NSTG;
            uint32_t bar = sb + ns * 8;
            uint32_t dst = sb + 1024u + (uint32_t)ns * STG_B;
            EXPECT_TX(bar, 2 * OPER_B);
            BULK16K(dst,          Asrc + (size_t)(kb + 2) * 4096, bar);
            BULK16K(dst + OPER_B, Bsrc + (size_t)(kb + 2) * 4096, bar);
        }

        const uint32_t sA = sb + 1024u + (uint32_t)slot * STG_B;
        const uint32_t sBm = sA + OPER_B;

        #pragma unroll
        for (int ks = 0; ks < 4; ks++) {
            const unsigned toff = (unsigned)(ks >> 1) * 8192u;
            unsigned a[4][4], b[4][2];
            #pragma unroll
            for (int i = 0; i < 4; i++) {
                int row = wm + i * 16 + aRowL;
                int cseg = (ks & 1) * 2 + aSegL;
                unsigned addr = sA + toff +
                    (unsigned)(row * 64 + (((cseg + ((row >> 1) & 3)) & 3) << 4));
                LDSM4(a[i][0], a[i][1], a[i][2], a[i][3], addr);
            }
            #pragma unroll
            for (int jp = 0; jp < 2; jp++) {
                int row = wn + jp * 16 + bRowL;
                int cseg = (ks & 1) * 2 + bSegL;
                unsigned addr = sBm + toff +
                    (unsigned)(row * 64 + (((cseg + ((row >> 1) & 3)) & 3) << 4));
                LDSM4(b[2*jp][0], b[2*jp][1], b[2*jp+1][0], b[2*jp+1][1], addr);
            }
            #pragma unroll
            for (int i = 0; i < 4; i++)
                #pragma unroll
                for (int j = 0; j < 4; j++) {
                    asm volatile(
                        "mma.sync.aligned.m16n8k8.row.col.f32.tf32.tf32.f32 "
                        "{%0,%1,%2,%3}, {%4,%5,%6,%7}, {%8,%9}, {%0,%1,%2,%3};\n"
                        : "+f"(c[i*4+j][0]), "+f"(c[i*4+j][1]),
                          "+f"(c[i*4+j][2]), "+f"(c[i*4+j][3])
                        : "r"(a[i][0]), "r"(a[i][1]), "r"(a[i][2]), "r"(a[i][3]),
                          "r"(b[j][0]), "r"(b[j][1]));
                }
        }
    }

    #pragma unroll
    for (int i = 0; i < 4; i++) {
        #pragma unroll
        for (int j = 0; j < 4; j++) {
            const int row = by * 128 + wm + i * 16 + g;
            const int col = bx * 128 + wn + j * 8 + 2 * t;
            if (col < N) {
                float b0 = 0.f, b1 = 0.f;
                if (bias) { b0 = __ldg(&bias[col]); b1 = __ldg(&bias[col + 1]); }
                float2 v0 = make_float2(c[i*4+j][0] + b0, c[i*4+j][1] + b1);
                float2 v1 = make_float2(c[i*4+j][2] + b0, c[i*4+j][3] + b1);
                *(float2*)&C[(size_t)row * N + col]       = v0;
                *(float2*)&C[(size_t)(row + 8) * N + col] = v1;
            }
        }
    }
}

// ---------------- causal depthwise conv1d (K=4) + SiLU ----------------
__global__ void conv_silu_kernel(const float* __restrict__ conv_w,
                                 const float* __restrict__ conv_b)
{
    int idx = blockIdx.x * blockDim.x + threadIdx.x;
    if (idx >= BL * CONVDIM) return;
    int c = idx % CONVDIM;
    int m = idx / CONVDIM;
    int l = m % LSEQ;

    float acc = conv_b[c];
    #pragma unroll
    for (int k = 0; k < KCONV; k++) {
        int lk = l - (KCONV - 1) + k;
        if (lk >= 0) {
            acc += g_proj[(size_t)(m - (KCONV - 1) + k) * PROJW + DMODEL + c]
                   * conv_w[c * KCONV + k];
        }
    }
    acc = acc / (1.f + expf(-acc));
    g_conv[(size_t)m * CONVDIM + c] = acc;
}

// ---------------- dt / dA ----------------
__global__ void dt_kernel(const float* __restrict__ A_log,
                          const float* __restrict__ dt_bias)
{
    int idx = blockIdx.x * blockDim.x + threadIdx.x;
    if (idx >= BL * HEADS) return;
    int h = idx % HEADS;
    int m = idx / HEADS;
    int b = m / LSEQ;
    int l = m % LSEQ;

    float raw = g_proj[(size_t)m * PROJW + DMODEL + CONVDIM + h] + dt_bias[h];
    float dt  = (raw > 20.f) ? raw : log1pf(expf(raw));
    float dA  = expf(dt * (-expf(A_log[h])));
    size_t o  = ((size_t)(b * HEADS + h)) * LSEQ + l;
    g_dt[o] = dt;
    g_dA[o] = dA;
}

// ================= chunked selective scan =================
#define SD 8

// Pass 1: local scan per (h, b, chunk) with H_start = 0.
__global__ __launch_bounds__(128, 1)
void scan_pass1(const float* __restrict__ D_param)
{
    const int h   = blockIdx.x;
    const int b   = blockIdx.y;
    const int cch = blockIdx.z;
    const int tid = threadIdx.x;
    const int bh  = b * HEADS + h;
    const int t0  = cch * CLEN;

    __shared__ float s_dt[CLEN];
    __shared__ float s_dA[CLEN];
    __shared__ __align__(16) float s_pipe[SD][128];

    s_dt[tid] = g_dt[(size_t)bh * LSEQ + t0 + tid];
    s_dA[tid] = g_dA[(size_t)bh * LSEQ + t0 + tid];

    const int p    = tid >> 1;
    const int half = tid & 1;
    const float Dh = D_param[h];

    unsigned long long hs[8];
    #pragma unroll
    for (int i = 0; i < 8; i++) hs[i] = 0ull;
    float acum = 1.f;

    const bool loader = (tid < 32);
    size_t srcoff = 0; int dstoff = 0;
    if (loader) {
        if (tid < 16) { srcoff = (size_t)h * HDIM + tid * 4; dstoff = tid * 4; }
        else          { srcoff = (size_t)DMODEL + (tid - 16) * 4; dstoff = 64 + (tid - 16) * 4; }
    }
    const float* convb = g_conv + ((size_t)b * LSEQ + t0) * CONVDIM;
    unsigned sbase = smem_u32(&s_pipe[0][0]);

    #pragma unroll
    for (int tt = 0; tt < SD - 1; tt++) {
        if (loader) {
            const float* src = convb + (size_t)tt * CONVDIM + srcoff;
            unsigned dst = sbase + (unsigned)(tt * 128 + dstoff) * 4u;
            asm volatile("cp.async.ca.shared.global [%0], [%1], 16;\n"
                         :: "r"(dst), "l"(src));
        }
        asm volatile("cp.async.commit_group;\n" ::: "memory");
    }

    float* yout = g_y + ((size_t)b * LSEQ + t0) * DMODEL + h * HDIM + p;

    for (int tc = 0; tc < CLEN; tc++) {
        asm volatile("cp.async.wait_group 6;\n" ::: "memory");
        __syncthreads();

        const int nt = tc + SD - 1;
        if (loader && nt < CLEN) {
            const float* src = convb + (size_t)nt * CONVDIM + srcoff;
            unsigned dst = sbase + (unsigned)((nt & (SD - 1)) * 128 + dstoff) * 4u;
            asm volatile("cp.async.ca.shared.global [%0], [%1], 16;\n"
                         :: "r"(dst), "l"(src));
        }
        asm volatile("cp.async.commit_group;\n" ::: "memory");

        const float* sl = s_pipe[tc & (SD - 1)];
        float xv  = sl[p];
        float dtv = s_dt[tc];
        float dav = s_dA[tc];
        acum *= dav;
        float coef = dtv * xv;
        unsigned long long c2 = pack2(coef, coef);
        unsigned long long d2 = pack2(dav, dav);
        const unsigned long long* B2 = (const unsigned long long*)(sl + 64) + half * 8;
        const unsigned long long* C2 = (const unsigned long long*)(sl + 96) + half * 8;

        unsigned long long acc0 = 0ull, acc1 = 0ull;
        #pragma unroll
        for (int i = 0; i < 8; i++) {
            unsigned long long u = mul2(c2, B2[i]);
            hs[i] = fma2v(d2, hs[i], u);
            if (i & 1) acc1 = fma2v(hs[i], C2[i], acc1);
            else       acc0 = fma2v(hs[i], C2[i], acc0);
        }
        unsigned long long s = add2(acc0, acc1);
        float mine = lo32(s) + hi32(s);
        float other = __shfl_xor_sync(0xffffffffu, mine, 1);
        if (half == 0) {
            yout[(size_t)tc * DMODEL] = mine + other + Dh * xv;
        }
    }

    // store chunk-end local state + dA product
    float* he = g_hend + ((size_t)bh * NCHUNK + cch) * 2048 + p * 32 + half * 16;
    #pragma unroll
    for (int i = 0; i < 8; i++) {
        float2 v = make_float2(lo32(hs[i]), hi32(hs[i]));
        *(float2*)(he + 2 * i) = v;
    }
    if (tid == 0) g_aend[(size_t)bh * NCHUNK + cch] = acum;
}

// Pass 2: sequential chunk-state recombination per (b,h).
__global__ __launch_bounds__(256)
void scan_pass2()
{
    const int bh  = blockIdx.x;
    const int e0  = threadIdx.x * 8;
    float4 H0 = make_float4(0.f, 0.f, 0.f, 0.f);
    float4 H1 = H0;

    for (int cch = 0; cch < NCHUNK; cch++) {
        size_t base = ((size_t)bh * NCHUNK + cch) * 2048 + e0;
        *(float4*)(g_hst + base)     = H0;
        *(float4*)(g_hst + base + 4) = H1;
        float ae = g_aend[(size_t)bh * NCHUNK + cch];
        float4 E0 = *(const float4*)(g_hend + base);
        float4 E1 = *(const float4*)(g_hend + base + 4);
        H0.x = ae * H0.x + E0.x;  H0.y = ae * H0.y + E0.y;
        H0.z = ae * H0.z + E0.z;  H0.w = ae * H0.w + E0.w;
        H1.x = ae * H1.x + E1.x;  H1.y = ae * H1.y + E1.y;
        H1.z = ae * H1.z + E1.z;  H1.w = ae * H1.w + E1.w;
    }
}

// Pass 3: parallel correction y_t += a_t * (H_start[p,:] . C_t), chunks 1..15.
__global__ __launch_bounds__(128)
void scan_pass3()
{
    const int h   = blockIdx.x;
    const int b   = blockIdx.y;
    const int cch = blockIdx.z + 1;
    const int tid = threadIdx.x;
    const int bh  = b * HEADS + h;
    const int t0  = cch * CLEN;

    __shared__ float Hs[2048];
    __shared__ float Cs[CLEN * 32];
    __shared__ float av[CLEN];

    {
        const float* hsrc = g_hst + ((size_t)bh * NCHUNK + cch) * 2048;
        #pragma unroll
        for (int i = 0; i < 16; i++) Hs[tid + i * 128] = hsrc[tid + i * 128];
        const float* cb = g_conv + ((size_t)b * LSEQ + t0) * CONVDIM + DMODEL + NSTATE;
        #pragma unroll
        for (int i = 0; i < 32; i++) {
            int j = tid + i * 128;
            Cs[j] = cb[(size_t)(j >> 5) * CONVDIM + (j & 31)];
        }
        av[tid] = g_dA[(size_t)bh * LSEQ + t0 + tid];
    }
    __syncthreads();

    // inclusive cumprod of av (Hillis-Steele)
    #pragma unroll
    for (int ofs = 1; ofs < CLEN; ofs <<= 1) {
        float v = (tid >= ofs) ? av[tid - ofs] : 1.f;
        __syncthreads();
        av[tid] *= v;
        __syncthreads();
    }

    const int p    = tid >> 1;
    const int half = tid & 1;
    unsigned long long Hr[8];
    {
        const unsigned long long* h2 = (const unsigned long long*)(Hs + p * 32 + half * 16);
        #pragma unroll
        for (int i = 0; i < 8; i++) Hr[i] = h2[i];
    }

    float* yout = g_y + ((size_t)b * LSEQ + t0) * DMODEL + h * HDIM + p;

    for (int tc = 0; tc < CLEN; tc++) {
        const unsigned long long* C2 =
            (const unsigned long long*)(Cs + tc * 32 + half * 16);
        unsigned long long acc0 = 0ull, acc1 = 0ull;
        #pragma unroll
        for (int i = 0; i < 8; i++) {
            if (i & 1) acc1 = fma2v(Hr[i], C2[i], acc1);
            else       acc0 = fma2v(Hr[i], C2[i], acc0);
        }
        unsigned long long s = add2(acc0, acc1);
        float mine = lo32(s) + hi32(s);
        float other = __shfl_xor_sync(0xffffffffu, mine, 1);
        if (half == 0) {
            yout[(size_t)tc * DMODEL] += av[tc] * (mine + other);
        }
    }
}

// ---------------- gated RMSNorm -> packed tf32 y ----------------
__global__ void __launch_bounds__(256)
rmsnorm_kernel(const float* __restrict__ norm_w)
{
    const int m   = blockIdx.x;
    const int tid = threadIdx.x;
    const float* yrow = g_y    + (size_t)m * DMODEL;
    const float* grow = g_proj + (size_t)m * PROJW;

    float v[8];
    float ss = 0.f;
    #pragma unroll
    for (int k = 0; k < 8; k++) {
        int j = tid + k * 256;
        float gt  = grow[j];
        float val = yrow[j] * (gt / (1.f + expf(-gt)));
        v[k] = val;
        ss += val * val;
    }
    #pragma unroll
    for (int o = 16; o > 0; o >>= 1) ss += __shfl_xor_sync(0xffffffffu, ss, o);

    __shared__ float sred[8];
    if ((tid & 31) == 0) sred[tid >> 5] = ss;
    __syncthreads();
    float tot = sred[0] + sred[1] + sred[2] + sred[3]
              + sred[4] + sred[5] + sred[6] + sred[7];
    float scale = rsqrtf(tot * (1.f / DMODEL) + 1e-6f);

    const int mb = m >> 7, r = m & 127;
    #pragma unroll
    for (int k = 0; k < 8; k++) {
        int j = tid + k * 256;
        float val = tf32r(v[k] * scale * norm_w[j]);
        g_ya[pk_off(mb, j >> 4, r, (j >> 2) & 3, j & 3)] = val;
    }
}

// ---------------- launch ----------------
extern "C" void kernel_launch(void* const* d_in, const int* in_sizes, int n_in,
                              void* d_out, int out_size)
{
    const float* x       = (const float*)d_in[0];
    const float* W_in    = (const float*)d_in[1];
    const float* b_in    = (const float*)d_in[2];
    const float* conv_w  = (const float*)d_in[3];
    const float* conv_b  = (const float*)d_in[4];
    const float* A_log   = (const float*)d_in[5];
    const float* dt_bias = (const float*)d_in[6];
    const float* D_par   = (const float*)d_in[7];
    const float* norm_w  = (const float*)d_in[8];
    const float* W_out   = (const float*)d_in[9];
    float* out = (float*)d_out;

    float *proj, *xa, *ya, *wa, *wb;
    cudaGetSymbolAddress((void**)&proj, g_proj);
    cudaGetSymbolAddress((void**)&xa,   g_xa);
    cudaGetSymbolAddress((void**)&ya,   g_ya);
    cudaGetSymbolAddress((void**)&wa,   g_wa);
    cudaGetSymbolAddress((void**)&wb,   g_wb);

    cudaFuncSetAttribute(tma_gemm, cudaFuncAttributeMaxDynamicSharedMemorySize,
                         GEMM_SMEM);

    // 0) pack x; transpose+pack W_in, W_out
    {
        int nseg = BL * DMODEL / 4;
        round_pack_kernel<<<(nseg + 255) / 256, 256>>>(x, xa);
        dim3 blk(32, 8);
        transpose_pack_kernel<<<dim3(PROJPAD / 32, DMODEL / 32), blk>>>(W_in, wa, PROJW);
        transpose_pack_kernel<<<dim3(DMODEL / 32, DMODEL / 32), blk>>>(W_out, wb, DMODEL);
    }
    // 1) proj = x @ W_in + b_in  (33 N-tiles)
    {
        dim3 grid(PROJPAD / 128, BL / 128);
        tma_gemm<<<grid, 256, GEMM_SMEM>>>(xa, wa, b_in, proj, PROJW);
    }
    // 2) conv + SiLU
    {
        int total = BL * CONVDIM;
        conv_silu_kernel<<<(total + 255) / 256, 256>>>(conv_w, conv_b);
    }
    // 3) dt / dA
    {
        int total = BL * HEADS;
        dt_kernel<<<(total + 255) / 256, 256>>>(A_log, dt_bias);
    }
    // 4) chunked selective scan
    scan_pass1<<<dim3(HEADS, BATCH, NCHUNK), 128>>>(D_par);
    scan_pass2<<<NBH, 256>>>();
    scan_pass3<<<dim3(HEADS, BATCH, NCHUNK - 1), 128>>>();
    // 5) gated RMSNorm (packs y as tf32)
    rmsnorm_kernel<<<BL, 256>>>(norm_w);
    // 6) out = y @ W_out
    {
        dim3 grid(DMODEL / 128, BL / 128);
        tma_gemm<<<grid, 256, GEMM_SMEM>>>(ya, wb, nullptr, out, DMODEL);
    }
}